// round 3
// baseline (speedup 1.0000x reference)
#include <cuda_runtime.h>

// dim=4096, MAX_DIM=32, N_COMP=10000.
// gather_idx/gather_sign: [32,32,32] row-major (k,i,j), int32/float32.
// Output: ricci[4096*4096] row-major + scalar trace at index 4096*4096.

#define DIMN 4096
#define MD 32

// One block per row i in [0,32). Each block:
//   - threads 0..31 compute r[i][j] = sum_k sgn[k,i,j]*comp[idx[k,i,j]]
//   - all 256 threads then write the FULL 4096-float row (gathered values
//     for cols 0..31, zeros elsewhere) with float4 stores.
//   - block 0 additionally recomputes the 32 diagonal elements, warp-reduces
//     them, and writes the trace scalar at index DIMN*DIMN.
// The memset in kernel_launch covers rows 32..4095 only, so the two
// operations touch disjoint memory.
__global__ __launch_bounds__(256)
void ricci_rows_kernel(const float* __restrict__ comp,
                       const int*   __restrict__ gidx,
                       const float* __restrict__ gsgn,
                       float* __restrict__ out)
{
    __shared__ float sh[MD];

    const int i = blockIdx.x;     // row 0..31
    const int t = threadIdx.x;    // 0..255

    if (t < MD) {
        float r = 0.f;
        #pragma unroll
        for (int k = 0; k < MD; k++) {
            const int o = k * (MD * MD) + i * MD + t;
            r += gsgn[o] * comp[gidx[o]];
        }
        sh[t] = r;
    }
    __syncthreads();

    // Write the full row: 4096 floats = 1024 float4 chunks, 4 per thread.
    float4* __restrict__ row4 =
        reinterpret_cast<float4*>(out + (size_t)i * DIMN);
    #pragma unroll
    for (int c = t; c < DIMN / 4; c += 256) {
        float4 v;
        if (c < MD / 4) {
            const int j = c * 4;
            v = make_float4(sh[j], sh[j + 1], sh[j + 2], sh[j + 3]);
        } else {
            v = make_float4(0.f, 0.f, 0.f, 0.f);
        }
        row4[c] = v;
    }

    // Block 0: trace scalar (redundant diagonal recompute, deterministic).
    if (i == 0 && t < 32) {
        float d = 0.f;
        #pragma unroll
        for (int k = 0; k < MD; k++) {
            const int o = k * (MD * MD) + t * MD + t;
            d += gsgn[o] * comp[gidx[o]];
        }
        #pragma unroll
        for (int off = 16; off > 0; off >>= 1)
            d += __shfl_down_sync(0xFFFFFFFFu, d, off);
        if (t == 0) out[(size_t)DIMN * DIMN] = d;
    }
}

extern "C" void kernel_launch(void* const* d_in, const int* in_sizes, int n_in,
                              void* d_out, int out_size)
{
    const float* comp = (const float*)d_in[0];   // components [10000] f32
    const int*   gidx = (const int*)  d_in[1];   // gather_idx [32,32,32] i32
    const float* gsgn = (const float*)d_in[2];   // gather_sign [32,32,32] f32

    float* out = (float*)d_out;

    // Zero rows 32..4095 only (rows 0..31 and the trailing scalar are fully
    // written by the kernel). Disjoint regions -> order-independent.
    const size_t skip = (size_t)MD * DIMN;                 // 32*4096 floats
    const size_t fill = (size_t)DIMN * DIMN - skip;        // rest of matrix
    cudaMemsetAsync(out + skip, 0, fill * sizeof(float));

    ricci_rows_kernel<<<MD, 256>>>(comp, gidx, gsgn, out);
}